// round 7
// baseline (speedup 1.0000x reference)
#include <cuda_runtime.h>
#include <cuda_bf16.h>
#include <math_constants.h>

#define DIM     2048
#define NHEADS  16
#define HD      128
#define BATCH   2
#define SEQ     4096
#define QKV_COLS (3*DIM)        // 6144
#define MROWS   (BATCH*SEQ)     // 8192

// ---------------------------------------------------------------------------
// Device-global scratch
// ---------------------------------------------------------------------------
__device__ float g_Q[(size_t)BATCH*NHEADS*SEQ*HD];   // pre-norm Q (fp32)
__device__ float g_K[(size_t)BATCH*NHEADS*SEQ*HD];   // pre-norm K (fp32)
__device__ __nv_bfloat16 g_Qh[(size_t)BATCH*NHEADS*SEQ*HD];
__device__ __nv_bfloat16 g_Ql[(size_t)BATCH*NHEADS*SEQ*HD];
__device__ __nv_bfloat16 g_Kh[(size_t)BATCH*NHEADS*SEQ*HD];
__device__ __nv_bfloat16 g_Kl[(size_t)BATCH*NHEADS*SEQ*HD];
__device__ __nv_bfloat16 g_Vh[(size_t)BATCH*NHEADS*SEQ*HD];
__device__ __nv_bfloat16 g_Vl[(size_t)BATCH*NHEADS*SEQ*HD];
__device__ __nv_bfloat16 g_xh[(size_t)MROWS*DIM];
__device__ __nv_bfloat16 g_xl[(size_t)MROWS*DIM];
__device__ __nv_bfloat16 g_wth[(size_t)QKV_COLS*DIM];  // W^T [n][k]
__device__ __nv_bfloat16 g_wtl[(size_t)QKV_COLS*DIM];

// ---------------------------------------------------------------------------
// PTX helpers (arch-neutral: mma.sync / ldmatrix / cp.async, sm_80+)
// ---------------------------------------------------------------------------
__device__ __forceinline__ unsigned smem_u32(const void* p) {
    unsigned a;
    asm("{ .reg .u64 t; cvta.to.shared.u64 t, %1; cvt.u32.u64 %0, t; }"
        : "=r"(a) : "l"(p));
    return a;
}
__device__ __forceinline__ void ldsm_x4(unsigned r[4], unsigned a) {
    asm volatile("ldmatrix.sync.aligned.m8n8.x4.shared.b16 {%0,%1,%2,%3}, [%4];"
                 : "=r"(r[0]), "=r"(r[1]), "=r"(r[2]), "=r"(r[3]) : "r"(a));
}
__device__ __forceinline__ void ldsm_x4_t(unsigned r[4], unsigned a) {
    asm volatile("ldmatrix.sync.aligned.m8n8.x4.trans.shared.b16 {%0,%1,%2,%3}, [%4];"
                 : "=r"(r[0]), "=r"(r[1]), "=r"(r[2]), "=r"(r[3]) : "r"(a));
}
__device__ __forceinline__ void mma16816(float c[4], const unsigned a[4],
                                         const unsigned b[2]) {
    asm volatile(
        "mma.sync.aligned.m16n8k16.row.col.f32.bf16.bf16.f32 "
        "{%0,%1,%2,%3}, {%4,%5,%6,%7}, {%8,%9}, {%0,%1,%2,%3};"
        : "+f"(c[0]), "+f"(c[1]), "+f"(c[2]), "+f"(c[3])
        : "r"(a[0]), "r"(a[1]), "r"(a[2]), "r"(a[3]), "r"(b[0]), "r"(b[1]));
}
__device__ __forceinline__ unsigned pack_bf16(float lo, float hi) {
    unsigned r;
    asm("cvt.rn.bf16x2.f32 %0, %1, %2;" : "=r"(r) : "f"(hi), "f"(lo));
    return r;
}
__device__ __forceinline__ float bf16_rn(float x) {
    return __bfloat162float(__float2bfloat16(x));
}
__device__ __forceinline__ float ex2(float x) {
    float y;
    asm("ex2.approx.f32 %0, %1;" : "=f"(y) : "f"(x));
    return y;
}
__device__ __forceinline__ void cp16(unsigned dst, const void* src) {
    asm volatile("cp.async.cg.shared.global [%0], [%1], 16;"
                 :: "r"(dst), "l"(src));
}
#define CP_COMMIT()  asm volatile("cp.async.commit_group;" ::: "memory")
#define CP_WAIT(n)   asm volatile("cp.async.wait_group %0;" :: "n"(n) : "memory")

// ---------------------------------------------------------------------------
// Kernel 0a: split x (fp32) into bf16 hi/lo
// ---------------------------------------------------------------------------
__global__ void convert_x_kernel(const float* __restrict__ x)
{
    size_t i = ((size_t)blockIdx.x * 256 + threadIdx.x) * 4;
    float4 v = *(const float4*)(x + i);
    float f[4] = {v.x, v.y, v.z, v.w};
    __nv_bfloat16 h[4], lo[4];
#pragma unroll
    for (int j = 0; j < 4; j++) {
        h[j] = __float2bfloat16(f[j]);
        lo[j] = __float2bfloat16(f[j] - __bfloat162float(h[j]));
    }
    *(uint2*)(g_xh + i) = *(uint2*)h;
    *(uint2*)(g_xl + i) = *(uint2*)lo;
}

// ---------------------------------------------------------------------------
// Kernel 0b: transpose W [k][n] -> [n][k], split into bf16 hi/lo
// ---------------------------------------------------------------------------
__global__ void convert_w_kernel(const float* __restrict__ W)
{
    __shared__ float tile[32][33];
    int tx = threadIdx.x, ty = threadIdx.y;          // block (32, 8)
    int n0 = blockIdx.x * 32, k0 = blockIdx.y * 32;
#pragma unroll
    for (int r = 0; r < 4; r++) {
        int k = k0 + ty + r * 8;
        tile[ty + r * 8][tx] = W[(size_t)k * QKV_COLS + n0 + tx];
    }
    __syncthreads();
#pragma unroll
    for (int r = 0; r < 4; r++) {
        int n = n0 + ty + r * 8;
        int k = k0 + tx;
        float v = tile[tx][ty + r * 8];
        __nv_bfloat16 h = __float2bfloat16(v);
        g_wth[(size_t)n * DIM + k] = h;
        g_wtl[(size_t)n * DIM + k] = __float2bfloat16(v - __bfloat162float(h));
    }
}

// ---------------------------------------------------------------------------
// Kernel 1: QKV GEMM via mma.sync bf16 x3, CTA 128x256, K-chunk 64,
// 2-stage cp.async pipeline (221 KB smem). 8 warps, warp tile 32x128.
// mma issue order is term-major so same-accumulator HMMA are >=4 apart.
// ---------------------------------------------------------------------------
#define G_STR    144                // smem row stride bytes (64 bf16 + 16B pad)
#define G_A_ARR  (128*G_STR)        // 18432
#define G_B_ARR  (256*G_STR)        // 36864
#define G_STAGE  (2*G_A_ARR + 2*G_B_ARR)   // 110592
#define GEMM_SMEM (2*G_STAGE)       // 221184

__global__ __launch_bounds__(256, 1) void qkv_gemm_mma_kernel(
    const float* __restrict__ bias)
{
    extern __shared__ char smem[];
    const unsigned sbase = smem_u32(smem);
    const int tid = threadIdx.x;
    const int wid = tid >> 5, lane = tid & 31;
    const int warp_m = wid >> 1, warp_n = wid & 1;
    const int gM0 = blockIdx.y << 7;
    const int gN0 = blockIdx.x << 8;
    const int l15 = lane & 15;

    float acc[2][16][4];
#pragma unroll
    for (int i = 0; i < 2; i++)
#pragma unroll
        for (int j = 0; j < 16; j++)
#pragma unroll
            for (int e = 0; e < 4; e++) acc[i][j][e] = 0.f;

    auto stage_load = [&](int st, int it) {
        unsigned sb = sbase + st * G_STAGE;
        int k0 = it * 64;
#pragma unroll
        for (int l = 0; l < 24; l++) {
            int t = tid + (l << 8);                // 0..6143
            if (t < 2048) {                        // A: Ah, Al
                int arr = t >> 10, w = t & 1023;
                int row = w >> 3, c4 = w & 7;
                const uint4* s = arr ? (const uint4*)g_xl : (const uint4*)g_xh;
                size_t gi = (((size_t)(gM0 + row) * DIM + k0) >> 3) + c4;
                cp16(sb + arr * G_A_ARR + row * G_STR + c4 * 16, s + gi);
            } else {                               // B: Bh, Bl
                int t2 = t - 2048;
                int arr = t2 >> 11, w = t2 & 2047;
                int row = w >> 3, c4 = w & 7;
                const uint4* s = arr ? (const uint4*)g_wtl : (const uint4*)g_wth;
                size_t gi = (((size_t)(gN0 + row) * DIM + k0) >> 3) + c4;
                cp16(sb + 2 * G_A_ARR + arr * G_B_ARR + row * G_STR + c4 * 16,
                     s + gi);
            }
        }
    };

    const int NIT = DIM / 64;        // 32
    stage_load(0, 0); CP_COMMIT();
    stage_load(1, 1); CP_COMMIT();

    for (int it = 0; it < NIT; ++it) {
        CP_WAIT(1);
        __syncthreads();

        unsigned sb = sbase + (it & 1) * G_STAGE;
        unsigned sAh = sb, sAl = sb + G_A_ARR;
        unsigned sBh = sb + 2 * G_A_ARR, sBl = sb + 2 * G_A_ARR + G_B_ARR;

#pragma unroll
        for (int ks = 0; ks < 4; ks++) {
            unsigned ah[2][4], al[2][4];
            int acol = ks * 16 + (lane >> 4) * 8;
#pragma unroll
            for (int i = 0; i < 2; i++) {
                int arow = warp_m * 32 + i * 16 + l15;
                ldsm_x4(ah[i], sAh + arow * G_STR + acol * 2);
                ldsm_x4(al[i], sAl + arow * G_STR + acol * 2);
            }
            int brow_off = (lane >> 4) * 8 + (lane & 7);
            int bcol = ks * 16 + ((lane >> 3) & 1) * 8;
#pragma unroll
            for (int jj = 0; jj < 8; jj++) {
                unsigned bh4[4], bl4[4];
                unsigned boff = (warp_n * 128 + jj * 16 + brow_off) * G_STR
                                + bcol * 2;
                ldsm_x4(bh4, sBh + boff);
                ldsm_x4(bl4, sBl + boff);
                // term-major: same-acc distance 4
                mma16816(acc[0][2*jj],   ah[0], bh4);
                mma16816(acc[0][2*jj+1], ah[0], bh4 + 2);
                mma16816(acc[1][2*jj],   ah[1], bh4);
                mma16816(acc[1][2*jj+1], ah[1], bh4 + 2);
                mma16816(acc[0][2*jj],   ah[0], bl4);
                mma16816(acc[0][2*jj+1], ah[0], bl4 + 2);
                mma16816(acc[1][2*jj],   ah[1], bl4);
                mma16816(acc[1][2*jj+1], ah[1], bl4 + 2);
                mma16816(acc[0][2*jj],   al[0], bh4);
                mma16816(acc[0][2*jj+1], al[0], bh4 + 2);
                mma16816(acc[1][2*jj],   al[1], bh4);
                mma16816(acc[1][2*jj+1], al[1], bh4 + 2);
            }
        }
        __syncthreads();                     // all warps done reading stage
        if (it + 2 < NIT) stage_load(it & 1, it + 2);
        CP_COMMIT();                         // unconditional: keeps count in sync
    }

    // Epilogue: bias + de-interleave scatter
    const int gr = lane >> 2, qc = (lane & 3) * 2;
#pragma unroll
    for (int i = 0; i < 2; i++) {
        int rbase = gM0 + warp_m * 32 + i * 16 + gr;
#pragma unroll
        for (int half = 0; half < 2; half++) {
            int row = rbase + half * 8;
            int b = row >> 12;
            int n = row & (SEQ - 1);
#pragma unroll
            for (int j = 0; j < 16; j++) {
                int cb = gN0 + warp_n * 128 + j * 8 + qc;
#pragma unroll
                for (int e = 0; e < 2; e++) {
                    int col = cb + e;
                    float v = acc[i][j][half * 2 + e] + __ldg(bias + col);
                    int h = col / 384;
                    int rem = col - h * 384;
                    int d = rem / 3;
                    int jj = rem - 3 * d;
                    size_t off = ((size_t)(b * NHEADS + h) * SEQ + n) * HD + d;
                    if (jj == 0)      g_Q[off] = v;
                    else if (jj == 1) g_K[off] = v;
                    else {
                        __nv_bfloat16 vh = __float2bfloat16(v);
                        g_Vh[off] = vh;
                        g_Vl[off] = __float2bfloat16(v - __bfloat162float(vh));
                    }
                }
            }
        }
    }
}

// ---------------------------------------------------------------------------
// Kernel 2: RMSNorm + RoPE, warp-per-row (float4 loads, shuffle-only reduce,
// RoPE pairs in-thread). Q pre-scaled by (1/sqrt(HD))*log2(e).
// Block 256 = 8 warps = 8 rows; grid = rows/8.
// ---------------------------------------------------------------------------
__global__ __launch_bounds__(256) void norm_rope_kernel(
    const float* __restrict__ rot, const float* __restrict__ qw,
    const float* __restrict__ kw)
{
    const int lane = threadIdx.x & 31;
    const int row = blockIdx.x * 8 + (threadIdx.x >> 5);
    const int n = row & (SEQ - 1);
    const size_t base = (size_t)row * HD + lane * 4;

    float4 q = *(const float4*)(g_Q + base);
    float4 k = *(const float4*)(g_K + base);

    float q2 = q.x*q.x + q.y*q.y + q.z*q.z + q.w*q.w;
    float k2 = k.x*k.x + k.y*k.y + k.z*k.z + k.w*k.w;
#pragma unroll
    for (int off = 16; off; off >>= 1) {
        q2 += __shfl_xor_sync(0xffffffffu, q2, off);
        k2 += __shfl_xor_sync(0xffffffffu, k2, off);
    }
    float qs = rsqrtf(q2 * (1.0f / HD) + 1e-6f);
    float ks = rsqrtf(k2 * (1.0f / HD) + 1e-6f);

    float4 qwv = *(const float4*)(qw + lane * 4);
    float4 kwv = *(const float4*)(kw + lane * 4);

    float qn0 = q.x * qs * qwv.x, qn1 = q.y * qs * qwv.y;
    float qn2 = q.z * qs * qwv.z, qn3 = q.w * qs * qwv.w;
    float kn0 = k.x * ks * kwv.x, kn1 = k.y * ks * kwv.y;
    float kn2 = k.z * ks * kwv.z, kn3 = k.w * ks * kwv.w;

    // rot for pairs i = 2*lane (elems 0,1) and 2*lane+1 (elems 2,3)
    const float* rp = rot + (size_t)n * 256 + lane * 8;
    float4 rA = *(const float4*)rp;        // [c00 c01 c10 c11] pair A
    float4 rB = *(const float4*)(rp + 4);  // pair B

    const float scale = 0.08838834764831845f * 1.4426950408889634f;
    float qo0 = (rA.x * qn0 + rA.y * qn1) * scale;
    float qo1 = (rA.z * qn0 + rA.w * qn1) * scale;
    float qo2 = (rB.x * qn2 + rB.y * qn3) * scale;
    float qo3 = (rB.z * qn2 + rB.w * qn3) * scale;
    float ko0 = rA.x * kn0 + rA.y * kn1;
    float ko1 = rA.z * kn0 + rA.w * kn1;
    float ko2 = rB.x * kn2 + rB.y * kn3;
    float ko3 = rB.z * kn2 + rB.w * kn3;

    uint2 qh = make_uint2(pack_bf16(qo0, qo1), pack_bf16(qo2, qo3));
    uint2 kh = make_uint2(pack_bf16(ko0, ko1), pack_bf16(ko2, ko3));
    uint2 ql = make_uint2(
        pack_bf16(qo0 - bf16_rn(qo0), qo1 - bf16_rn(qo1)),
        pack_bf16(qo2 - bf16_rn(qo2), qo3 - bf16_rn(qo3)));
    uint2 kl = make_uint2(
        pack_bf16(ko0 - bf16_rn(ko0), ko1 - bf16_rn(ko1)),
        pack_bf16(ko2 - bf16_rn(ko2), ko3 - bf16_rn(ko3)));

    *(uint2*)(g_Qh + base) = qh;
    *(uint2*)(g_Ql + base) = ql;
    *(uint2*)(g_Kh + base) = kh;
    *(uint2*)(g_Kl + base) = kl;
}

// ---------------------------------------------------------------------------
// Kernel 3: Flash attention, BM=128 (8 warps), BN=64, D=128.
// Q fragments register-resident; K/V 3-stage cp.async pipeline with EARLY
// prefetch issue (right after top-of-loop barrier). No-max softmax (Q,K are
// RMS-normalized so exp2 args are bounded). mma issue order term-major.
// ---------------------------------------------------------------------------
#define A_STR    272                 // smem row stride bytes (128 bf16 + pad)
#define A_ARR    (64*A_STR)          // 17408 (64-row array)
#define A_STAGE  (4*A_ARR)           // Kh,Kl,Vh,Vl  = 69632
#define ATT_SMEM (3*A_STAGE)         // 208896

__global__ __launch_bounds__(256, 1) void attn_mma_kernel(float* __restrict__ out)
{
    extern __shared__ char smem[];
    const unsigned sbase = smem_u32(smem);
    const int bh = blockIdx.y;
    const int q0 = blockIdx.x << 7;          // 128 rows per CTA
    const int tid = threadIdx.x;
    const int wid = tid >> 5, lane = tid & 31;
    const int l15 = lane & 15;
    const int gr = lane >> 2, qc = (lane & 3) * 2;

    // --- Load Q tile (128 rows, hi/lo) into stage-0 region ---
    {
        const uint4* Qh4 = (const uint4*)g_Qh;
        const uint4* Ql4 = (const uint4*)g_Ql;
#pragma unroll
        for (int l = 0; l < 16; l++) {
            int t = tid + (l << 8);            // 0..4095
            int arr = t >> 11;                 // 0: hi, 1: lo
            int w = t & 2047;
            int row = w >> 4, c = w & 15;
            size_t gi = (((size_t)bh * SEQ + q0 + row) * HD >> 3) + c;
            const uint4* s = arr ? Ql4 : Qh4;
            cp16(sbase + arr * (128 * A_STR) + row * A_STR + c * 16, s + gi);
        }
    }
    CP_COMMIT();
    CP_WAIT(0);
    __syncthreads();

    // --- Hoist Q fragments to registers (once) ---
    unsigned qfh[8][4], qfl[8][4];
    {
        int arow = wid * 16 + l15;
#pragma unroll
        for (int ks = 0; ks < 8; ks++) {
            int acol = ks * 16 + (lane >> 4) * 8;
            ldsm_x4(qfh[ks], sbase + arow * A_STR + acol * 2);
            ldsm_x4(qfl[ks], sbase + 128 * A_STR + arow * A_STR + acol * 2);
        }
    }
    __syncthreads();   // staging free before K/V pipeline reuses it

    const uint4* Kh4 = (const uint4*)g_Kh;
    const uint4* Kl4 = (const uint4*)g_Kl;
    const uint4* Vh4 = (const uint4*)g_Vh;
    const uint4* Vl4 = (const uint4*)g_Vl;

    auto stage_load = [&](int st, int kt) {
        unsigned sb = sbase + st * A_STAGE;
#pragma unroll
        for (int l = 0; l < 16; l++) {
            int t = tid + (l << 8);            // 0..4095
            int arr = t >> 10;                 // 0..3: Kh,Kl,Vh,Vl
            int w = t & 1023;
            int row = w >> 4, c = w & 15;
            size_t gi = (((size_t)bh * SEQ + kt * 64 + row) * HD >> 3) + c;
            const uint4* s = (arr == 0) ? Kh4 : (arr == 1) ? Kl4
                             : (arr == 2) ? Vh4 : Vl4;
            cp16(sb + arr * A_ARR + row * A_STR + c * 16, s + gi);
        }
    };

    float O[16][4];
#pragma unroll
    for (int n = 0; n < 16; n++)
#pragma unroll
        for (int e = 0; e < 4; e++) O[n][e] = 0.f;
    float l0 = 0.f, l1 = 0.f;              // per-thread partial row sums

    const int NKT = SEQ / 64;   // 64
    stage_load(0, 0); CP_COMMIT();
    stage_load(1, 1); CP_COMMIT();

    int buf = 0;
    for (int kt = 0; kt < NKT; kt++) {
        CP_WAIT(1);
        __syncthreads();        // stage kt visible; all warps done with kt-1

        // EARLY prefetch: buffer (buf+2)%3 held kt-1, which the barrier above
        // just proved everyone is done with. Issue loads before compute so
        // they have the whole iteration to land.
        {
            int nb = buf + 2; if (nb >= 3) nb -= 3;
            if (kt + 2 < NKT) stage_load(nb, kt + 2);
            CP_COMMIT();
        }

        unsigned sb = sbase + buf * A_STAGE;
        unsigned sKh = sb, sKl = sb + A_ARR;
        unsigned sVh = sb + 2 * A_ARR, sVl = sb + 3 * A_ARR;

        // --- S = Q K^T (3-term), term-major mma order ---
        float S[8][4];
#pragma unroll
        for (int j = 0; j < 8; j++)
#pragma unroll
            for (int e = 0; e < 4; e++) S[j][e] = 0.f;

        {
            int brow_off = (lane >> 4) * 8 + (lane & 7);
            int g_kh = ((lane >> 3) & 1) * 8;
#pragma unroll
            for (int ks = 0; ks < 8; ks++) {
                int bcol = ks * 16 + g_kh;
                unsigned kh4[4][4], kl4[4][4];
#pragma unroll
                for (int jj = 0; jj < 4; jj++) {
                    unsigned boff = (jj * 16 + brow_off) * A_STR + bcol * 2;
                    ldsm_x4(kh4[jj], sKh + boff);
                    ldsm_x4(kl4[jj], sKl + boff);
                }
#pragma unroll
                for (int jj = 0; jj < 4; jj++) {
                    mma16816(S[2*jj],   qfh[ks], kh4[jj]);
                    mma16816(S[2*jj+1], qfh[ks], kh4[jj] + 2);
                }
#pragma unroll
                for (int jj = 0; jj < 4; jj++) {
                    mma16816(S[2*jj],   qfh[ks], kl4[jj]);
                    mma16816(S[2*jj+1], qfh[ks], kl4[jj] + 2);
                }
#pragma unroll
                for (int jj = 0; jj < 4; jj++) {
                    mma16816(S[2*jj],   qfl[ks], kh4[jj]);
                    mma16816(S[2*jj+1], qfl[ks], kh4[jj] + 2);
                }
            }
        }

        // --- No-max softmax: P = exp2(S); accumulate partial l ---
#pragma unroll
        for (int j = 0; j < 8; j++) {
            S[j][0] = ex2(S[j][0]);
            S[j][1] = ex2(S[j][1]);
            S[j][2] = ex2(S[j][2]);
            S[j][3] = ex2(S[j][3]);
            l0 += S[j][0] + S[j][1];
            l1 += S[j][2] + S[j][3];
        }

        // --- O += P V (3-term), nn processed in pairs for acc distance ---
        {
            int vrow_off = (((lane >> 3) & 1) * 8) + (lane & 7);
            int vcol_off = (lane >> 4) * 16;
#pragma unroll
            for (int t = 0; t < 4; t++) {
                unsigned ph[4], pl[4];
                const float* s0 = S[2 * t];
                const float* s1 = S[2 * t + 1];
                ph[0] = pack_bf16(s0[0], s0[1]);
                ph[1] = pack_bf16(s0[2], s0[3]);
                ph[2] = pack_bf16(s1[0], s1[1]);
                ph[3] = pack_bf16(s1[2], s1[3]);
                pl[0] = pack_bf16(s0[0]-bf16_rn(s0[0]), s0[1]-bf16_rn(s0[1]));
                pl[1] = pack_bf16(s0[2]-bf16_rn(s0[2]), s0[3]-bf16_rn(s0[3]));
                pl[2] = pack_bf16(s1[0]-bf16_rn(s1[0]), s1[1]-bf16_rn(s1[1]));
                pl[3] = pack_bf16(s1[2]-bf16_rn(s1[2]), s1[3]-bf16_rn(s1[3]));
#pragma unroll
                for (int nn = 0; nn < 8; nn += 2) {
                    unsigned vha[4], vla[4], vhb[4], vlb[4];
                    unsigned va = (t * 16 + vrow_off) * A_STR
                                  + nn * 32 + vcol_off;
                    ldsm_x4_t(vha, sVh + va);
                    ldsm_x4_t(vla, sVl + va);
                    ldsm_x4_t(vhb, sVh + va + 32);
                    ldsm_x4_t(vlb, sVl + va + 32);
                    // term-major across 4 accumulators
                    mma16816(O[2*nn],   ph, vha);
                    mma16816(O[2*nn+1], ph, vha + 2);
                    mma16816(O[2*nn+2], ph, vhb);
                    mma16816(O[2*nn+3], ph, vhb + 2);
                    mma16816(O[2*nn],   ph, vla);
                    mma16816(O[2*nn+1], ph, vla + 2);
                    mma16816(O[2*nn+2], ph, vlb);
                    mma16816(O[2*nn+3], ph, vlb + 2);
                    mma16816(O[2*nn],   pl, vha);
                    mma16816(O[2*nn+1], pl, vha + 2);
                    mma16816(O[2*nn+2], pl, vhb);
                    mma16816(O[2*nn+3], pl, vhb + 2);
                }
            }
        }

        if (++buf == 3) buf = 0;
    }

    // --- Final l reduction across the 4 lanes of each row group ---
    l0 += __shfl_xor_sync(0xffffffffu, l0, 1);
    l0 += __shfl_xor_sync(0xffffffffu, l0, 2);
    l1 += __shfl_xor_sync(0xffffffffu, l1, 1);
    l1 += __shfl_xor_sync(0xffffffffu, l1, 2);

    // --- Write output ---
    const int b = bh >> 4, h = bh & 15;
    float inv0 = __fdividef(1.0f, l0);
    float inv1 = __fdividef(1.0f, l1);
    int n0g = q0 + wid * 16 + gr;
    float* o0 = out + ((size_t)b * SEQ + n0g) * DIM + h * HD;
    float* o1 = out + ((size_t)b * SEQ + n0g + 8) * DIM + h * HD;
#pragma unroll
    for (int n = 0; n < 16; n++) {
        int d = n * 8 + qc;
        float2 w0 = make_float2(O[n][0] * inv0, O[n][1] * inv0);
        float2 w1 = make_float2(O[n][2] * inv1, O[n][3] * inv1);
        *(float2*)(o0 + d) = w0;
        *(float2*)(o1 + d) = w1;
    }
}

// ---------------------------------------------------------------------------
extern "C" void kernel_launch(void* const* d_in, const int* in_sizes, int n_in,
                              void* d_out, int out_size)
{
    const float* x    = (const float*)d_in[0];
    const float* rot  = (const float*)d_in[1];
    const float* W    = (const float*)d_in[2];
    const float* bias = (const float*)d_in[3];
    const float* qw   = (const float*)d_in[4];
    const float* kw   = (const float*)d_in[5];
    float* out = (float*)d_out;

    convert_x_kernel<<<(MROWS * DIM) / (256 * 4), 256>>>(x);
    convert_w_kernel<<<dim3(QKV_COLS / 32, DIM / 32), dim3(32, 8)>>>(W);

    cudaFuncSetAttribute(qkv_gemm_mma_kernel,
                         cudaFuncAttributeMaxDynamicSharedMemorySize, GEMM_SMEM);
    qkv_gemm_mma_kernel<<<dim3(QKV_COLS / 256, MROWS / 128), 256, GEMM_SMEM>>>(bias);

    norm_rope_kernel<<<(BATCH * NHEADS * SEQ) / 8, 256>>>(rot, qw, kw);

    cudaFuncSetAttribute(attn_mma_kernel,
                         cudaFuncAttributeMaxDynamicSharedMemorySize, ATT_SMEM);
    attn_mma_kernel<<<dim3(SEQ / 128, BATCH * NHEADS), 256, ATT_SMEM>>>(out);
}